// round 3
// baseline (speedup 1.0000x reference)
#include <cuda_runtime.h>
#include <cuda_bf16.h>

// E8 lattice quantizer. 2 rows per thread, loads front-batched for MLP=4.
//
// Per coset (off in {0, 0.5}):
//   f_i = rint(x_i - off); d_i = (x_i - off) - f_i
//   argmax chain tracks signed d_k (first max, strict >) and one-hot bitmask.
//   fix = (d_k < 0) ? -1 : +1 ; g_even = ((int)sum(f) + (int)fix) & 1 == 0
//   closed-form dist: s = g_even ? sumd2 + 1 - 2|d_k| : sumd2
// Pick coset by s2 < s1 (ties -> coset 1), materialize output once.

struct Coset {
    float s;    // distance^2 of chosen point
    float add;  // g_even ? fix : 0
    int   oh;   // one-hot mask of argmax coordinate
};

__device__ __forceinline__ Coset d8_pass(const float x[8], float off, float fout[8]) {
    float dk, sumf, sumd2;
    int oh = 1;
    {
        float xi = x[0] - off;
        float fi = rintf(xi);          // round-half-to-even == jnp.round
        float di = xi - fi;
        fout[0] = fi + off;
        sumf  = fi;
        sumd2 = di * di;
        dk    = di;
    }
#pragma unroll
    for (int i = 1; i < 8; i++) {
        float xi = x[i] - off;
        float fi = rintf(xi);
        float di = xi - fi;
        fout[i] = fi + off;
        sumf += fi;
        sumd2 = fmaf(di, di, sumd2);
        if (fabsf(di) > fabsf(dk)) { dk = di; oh = 1 << i; }  // strict >: first max
    }
    float fix = (dk < 0.0f) ? -1.0f : 1.0f;   // d_k == 0 -> +1
    int sg = (int)sumf + (int)fix;            // exact small integers
    bool ge = ((sg & 1) == 0);
    float m = fabsf(dk);
    Coset c;
    c.s   = ge ? fmaf(-2.0f, m, sumd2 + 1.0f) : sumd2;
    c.add = ge ? fix : 0.0f;
    c.oh  = oh;
    return c;
}

__device__ __forceinline__ void e8_row(const float x[8], float4& o0, float4& o1) {
    float y1[8], y2[8];
    Coset c1 = d8_pass(x, 0.0f, y1);
    Coset c2 = d8_pass(x, 0.5f, y2);

    bool use2 = (c2.s < c1.s);   // strict: ties -> coset 1
    float add = use2 ? c2.add : c1.add;
    int   oh  = use2 ? c2.oh  : c1.oh;

    float y[8];
#pragma unroll
    for (int i = 0; i < 8; i++) {
        float fi = use2 ? y2[i] : y1[i];
        if (oh & (1 << i)) fi += add;
        y[i] = fi;
    }
    o0.x = y[0]; o0.y = y[1]; o0.z = y[2]; o0.w = y[3];
    o1.x = y[4]; o1.y = y[5]; o1.z = y[6]; o1.w = y[7];
}

__global__ void __launch_bounds__(256) e8_quantize_kernel(
    const float4* __restrict__ in4, float4* __restrict__ out4, int n_pairs) {
    int t = blockIdx.x * blockDim.x + threadIdx.x;
    if (t >= n_pairs) return;

    // Front-batch all 4 loads: MLP=4 per thread.
    float4 a0 = __ldcs(&in4[4 * t + 0]);
    float4 a1 = __ldcs(&in4[4 * t + 1]);
    float4 b0 = __ldcs(&in4[4 * t + 2]);
    float4 b1 = __ldcs(&in4[4 * t + 3]);

    {
        float xa[8] = {a0.x, a0.y, a0.z, a0.w, a1.x, a1.y, a1.z, a1.w};
        float4 o0, o1;
        e8_row(xa, o0, o1);
        __stcs(&out4[4 * t + 0], o0);
        __stcs(&out4[4 * t + 1], o1);
    }
    {
        float xb[8] = {b0.x, b0.y, b0.z, b0.w, b1.x, b1.y, b1.z, b1.w};
        float4 o0, o1;
        e8_row(xb, o0, o1);
        __stcs(&out4[4 * t + 2], o0);
        __stcs(&out4[4 * t + 3], o1);
    }
}

extern "C" void kernel_launch(void* const* d_in, const int* in_sizes, int n_in,
                              void* d_out, int out_size) {
    const float4* in4 = (const float4*)d_in[0];
    float4* out4 = (float4*)d_out;
    int n_rows = in_sizes[0] / 8;
    int n_pairs = n_rows / 2;                 // N = 8388608, even
    int extra = n_rows - 2 * n_pairs;         // guard for odd N (not hit here)
    int threads = 256;
    int blocks = (n_pairs + threads - 1) / threads;
    e8_quantize_kernel<<<blocks, threads>>>(in4, out4, n_pairs);
    if (extra) {
        // odd tail: treat last row as a "pair" of one by reusing kernel on 1 row
        // (not needed for this problem size; kept for safety, zero-cost when extra==0)
    }
}

// round 4
// speedup vs baseline: 1.0647x; 1.0647x over previous
#include <cuda_runtime.h>
#include <cuda_bf16.h>

// E8 lattice quantizer. 2 rows per thread via SPLIT-ARRAY streams:
// thread t handles row t and row t + n_half. Each LDG.128 keeps the
// 32B-per-thread warp stride of the best (82us) kernel, but the warp
// now has 4 outstanding loads (MLP=4) instead of 2.

struct Coset {
    float s;    // distance^2 of chosen point
    float add;  // g_even ? fix : 0
    int   oh;   // one-hot mask of argmax coordinate
};

__device__ __forceinline__ Coset d8_pass(const float x[8], float off, float fout[8]) {
    float dk, sumf, sumd2;
    int oh = 1;
    {
        float xi = x[0] - off;
        float fi = rintf(xi);          // round-half-to-even == jnp.round
        float di = xi - fi;
        fout[0] = fi + off;
        sumf  = fi;
        sumd2 = di * di;
        dk    = di;
    }
#pragma unroll
    for (int i = 1; i < 8; i++) {
        float xi = x[i] - off;
        float fi = rintf(xi);
        float di = xi - fi;
        fout[i] = fi + off;
        sumf += fi;
        sumd2 = fmaf(di, di, sumd2);
        if (fabsf(di) > fabsf(dk)) { dk = di; oh = 1 << i; }  // strict >: first max
    }
    float fix = (dk < 0.0f) ? -1.0f : 1.0f;   // d_k == 0 -> +1
    int sg = (int)sumf + (int)fix;            // exact small integers
    bool ge = ((sg & 1) == 0);
    float m = fabsf(dk);
    Coset c;
    c.s   = ge ? fmaf(-2.0f, m, sumd2 + 1.0f) : sumd2;
    c.add = ge ? fix : 0.0f;
    c.oh  = oh;
    return c;
}

__device__ __forceinline__ void e8_row(const float x[8], float4& o0, float4& o1) {
    float y1[8], y2[8];
    Coset c1 = d8_pass(x, 0.0f, y1);
    Coset c2 = d8_pass(x, 0.5f, y2);

    bool use2 = (c2.s < c1.s);   // strict: ties -> coset 1
    float add = use2 ? c2.add : c1.add;
    int   oh  = use2 ? c2.oh  : c1.oh;

    float y[8];
#pragma unroll
    for (int i = 0; i < 8; i++) {
        float fi = use2 ? y2[i] : y1[i];
        if (oh & (1 << i)) fi += add;
        y[i] = fi;
    }
    o0.x = y[0]; o0.y = y[1]; o0.z = y[2]; o0.w = y[3];
    o1.x = y[4]; o1.y = y[5]; o1.z = y[6]; o1.w = y[7];
}

__global__ void __launch_bounds__(256) e8_quantize_kernel(
    const float4* __restrict__ in4, float4* __restrict__ out4, int n_half) {
    int t = blockIdx.x * blockDim.x + threadIdx.x;
    if (t >= n_half) return;

    long ia = 2L * t;                    // row t        (stream A)
    long ib = 2L * (t + (long)n_half);   // row t+n_half (stream B)

    // Front-batch 4 loads; each instruction has the proven 32B warp stride.
    float4 a0 = __ldcs(&in4[ia + 0]);
    float4 a1 = __ldcs(&in4[ia + 1]);
    float4 b0 = __ldcs(&in4[ib + 0]);
    float4 b1 = __ldcs(&in4[ib + 1]);

    {
        float xa[8] = {a0.x, a0.y, a0.z, a0.w, a1.x, a1.y, a1.z, a1.w};
        float4 o0, o1;
        e8_row(xa, o0, o1);
        __stcs(&out4[ia + 0], o0);
        __stcs(&out4[ia + 1], o1);
    }
    {
        float xb[8] = {b0.x, b0.y, b0.z, b0.w, b1.x, b1.y, b1.z, b1.w};
        float4 o0, o1;
        e8_row(xb, o0, o1);
        __stcs(&out4[ib + 0], o0);
        __stcs(&out4[ib + 1], o1);
    }
}

// Tail kernel for odd row counts (not hit for N=8388608, kept for safety).
__global__ void e8_quantize_tail(const float4* __restrict__ in4,
                                 float4* __restrict__ out4, int row) {
    float4 a0 = in4[2L * row + 0];
    float4 a1 = in4[2L * row + 1];
    float x[8] = {a0.x, a0.y, a0.z, a0.w, a1.x, a1.y, a1.z, a1.w};
    float4 o0, o1;
    e8_row(x, o0, o1);
    out4[2L * row + 0] = o0;
    out4[2L * row + 1] = o1;
}

extern "C" void kernel_launch(void* const* d_in, const int* in_sizes, int n_in,
                              void* d_out, int out_size) {
    const float4* in4 = (const float4*)d_in[0];
    float4* out4 = (float4*)d_out;
    int n_rows = in_sizes[0] / 8;
    int n_half = n_rows / 2;
    int threads = 256;
    int blocks = (n_half + threads - 1) / threads;
    e8_quantize_kernel<<<blocks, threads>>>(in4, out4, n_half);
    if (n_rows & 1) {
        e8_quantize_tail<<<1, 1>>>(in4, out4, n_rows - 1);
    }
}

// round 5
// speedup vs baseline: 1.1233x; 1.0550x over previous
#include <cuda_runtime.h>
#include <cuda_bf16.h>

// E8 lattice quantizer. 1 row/thread (best structure: 32 regs, high occ),
// upgraded to 256-bit loads/stores (sm_100+ ld/st.global.v8.f32):
// one LDG.256 + one STG.256 per row, warp-contiguous 1024B per instruction.

struct Coset {
    float s;    // distance^2 of chosen point
    float add;  // g_even ? fix : 0
    int   oh;   // one-hot mask of argmax coordinate
};

__device__ __forceinline__ Coset d8_pass(const float x[8], float off, float fout[8]) {
    float dk, sumf, sumd2;
    int oh = 1;
    {
        float xi = x[0] - off;
        float fi = rintf(xi);          // round-half-to-even == jnp.round
        float di = xi - fi;
        fout[0] = fi + off;
        sumf  = fi;
        sumd2 = di * di;
        dk    = di;
    }
#pragma unroll
    for (int i = 1; i < 8; i++) {
        float xi = x[i] - off;
        float fi = rintf(xi);
        float di = xi - fi;
        fout[i] = fi + off;
        sumf += fi;
        sumd2 = fmaf(di, di, sumd2);
        if (fabsf(di) > fabsf(dk)) { dk = di; oh = 1 << i; }  // strict >: first max
    }
    float fix = (dk < 0.0f) ? -1.0f : 1.0f;   // d_k == 0 -> +1
    int sg = (int)sumf + (int)fix;            // exact small integers
    bool ge = ((sg & 1) == 0);
    float m = fabsf(dk);
    Coset c;
    c.s   = ge ? fmaf(-2.0f, m, sumd2 + 1.0f) : sumd2;
    c.add = ge ? fix : 0.0f;
    c.oh  = oh;
    return c;
}

__device__ __forceinline__ void ldg256(const float* p, float x[8]) {
    asm volatile("ld.global.v8.f32 {%0,%1,%2,%3,%4,%5,%6,%7}, [%8];"
                 : "=f"(x[0]), "=f"(x[1]), "=f"(x[2]), "=f"(x[3]),
                   "=f"(x[4]), "=f"(x[5]), "=f"(x[6]), "=f"(x[7])
                 : "l"(p));
}

__device__ __forceinline__ void stg256(float* p, const float y[8]) {
    asm volatile("st.global.v8.f32 [%0], {%1,%2,%3,%4,%5,%6,%7,%8};"
                 :: "l"(p),
                    "f"(y[0]), "f"(y[1]), "f"(y[2]), "f"(y[3]),
                    "f"(y[4]), "f"(y[5]), "f"(y[6]), "f"(y[7])
                 : "memory");
}

__global__ void __launch_bounds__(256) e8_quantize_kernel(
    const float* __restrict__ in, float* __restrict__ out, int n_rows) {
    int t = blockIdx.x * blockDim.x + threadIdx.x;
    if (t >= n_rows) return;

    float x[8];
    ldg256(in + 8L * t, x);

    float y1[8], y2[8];
    Coset c1 = d8_pass(x, 0.0f, y1);
    Coset c2 = d8_pass(x, 0.5f, y2);

    bool use2 = (c2.s < c1.s);   // strict: ties -> coset 1
    float add = use2 ? c2.add : c1.add;
    int   oh  = use2 ? c2.oh  : c1.oh;

    float y[8];
#pragma unroll
    for (int i = 0; i < 8; i++) {
        float fi = use2 ? y2[i] : y1[i];
        if (oh & (1 << i)) fi += add;
        y[i] = fi;
    }

    stg256(out + 8L * t, y);
}

extern "C" void kernel_launch(void* const* d_in, const int* in_sizes, int n_in,
                              void* d_out, int out_size) {
    const float* in = (const float*)d_in[0];
    float* out = (float*)d_out;
    int n_rows = in_sizes[0] / 8;
    int threads = 256;
    int blocks = (n_rows + threads - 1) / threads;
    e8_quantize_kernel<<<blocks, threads>>>(in, out, n_rows);
}